// round 8
// baseline (speedup 1.0000x reference)
#include <cuda_runtime.h>
#include <cuda_bf16.h>
#include <cstdint>

// BispectrumCalculator: target [B=32, T=4, N=512] f32
//   y = fft(target);  Bx[k,l] = y[k]*conj(y[l])*y[(l-k)%N]
//   source[b,{re,im},k,l] = mean_t Bx;  out = concat(source, target)
//
// Real input => Bx[l,k] = conj(Bx[k,l]) (Hermitian): compute upper-triangle
// 64x64 tiles only; emit mirror tile via padded smem transpose.
// This revision: 4 l-outputs per thread -> STG.128 stores, amortized k-broadcasts.

#define B_DIM 32
#define T_DIM 4
#define N_DIM 512
#define NROWS (B_DIM * T_DIM)                           // 128
#define SRC_ELEMS ((size_t)B_DIM * 2 * N_DIM * N_DIM)   // 16,777,216
#define TGT_ELEMS (B_DIM * T_DIM * N_DIM)               // 65,536
#define TILE 64
#define NT (N_DIM / TILE)                               // 8
#define NTRI (NT * (NT + 1) / 2)                        // 36
#define NN (N_DIM * N_DIM)                              // 262,144
#define TPAD 65                                         // transpose row pad

// FFT results, t-paired: g_y2[b][p][n] = float4(y_{2p}[n].re, y_{2p}[n].im,
//                                               y_{2p+1}[n].re, y_{2p+1}[n].im)
__device__ float4 g_y2[B_DIM * 2 * N_DIM];

// ---------------------------------------------------------------------------
// Kernel 1: 512-point radix-2 DIT FFT, one row per block, 256 threads.
//           Also copies the target tail into the output.
// ---------------------------------------------------------------------------
__global__ void fft512_kernel(const float* __restrict__ x,
                              float* __restrict__ out, int copy_tail) {
    __shared__ float2 s[N_DIM];
    const int row = blockIdx.x;          // 0..127
    const int tid = threadIdx.x;         // 0..255
    const float* xr = x + row * N_DIM;

    if (copy_tail && tid < 128) {        // 128 float4 = 512 floats per row
        ((float4*)(out + SRC_ELEMS + (size_t)row * N_DIM))[tid] =
            ((const float4*)xr)[tid];
    }

    #pragma unroll
    for (int i = tid; i < N_DIM; i += 256) {
        int r = __brev((unsigned)i) >> 23;   // 9-bit bit reversal
        s[r] = make_float2(xr[i], 0.0f);
    }
    __syncthreads();

    #pragma unroll
    for (int len = 2; len <= N_DIM; len <<= 1) {
        int half = len >> 1;
        int j    = tid & (half - 1);
        int grp  = tid / half;
        int base = grp * len;
        float ang = -6.283185307179586f * (float)j / (float)len;
        float wr, wi;
        __sincosf(ang, &wi, &wr);
        float2 a = s[base + j];
        float2 b = s[base + j + half];
        float tr = wr * b.x - wi * b.y;
        float ti = wr * b.y + wi * b.x;
        s[base + j]        = make_float2(a.x + tr, a.y + ti);
        s[base + j + half] = make_float2(a.x - tr, a.y - ti);
        __syncthreads();
    }

    // Paired store: row = b*4 + t -> half (t&1) of float4 at [b*2 + t/2][i]
    const int b = row >> 2, t = row & 3;
    float2* dst = (float2*)g_y2 + ((size_t)((b * 2 + (t >> 1)) * N_DIM)) * 2 + (t & 1);
    #pragma unroll
    for (int i = tid; i < N_DIM; i += 256)
        dst[i * 2] = s[i];
}

// ---------------------------------------------------------------------------
// Kernel 2: bispectrum on upper-triangle tiles, 4 l per thread.
//   grid = (32, 36); block = 256 threads.
//   thread: tx4 = tid&15 -> l_loc = 4*tx4;  ty = tid>>4 -> kloc = 16s + ty.
//   smem: sy[2][512] float4 (16KB) + stre/stim transpose [64][65] (33.3KB).
// ---------------------------------------------------------------------------
__global__ __launch_bounds__(256, 3)
void bispec_kernel(float* __restrict__ out) {
    extern __shared__ float dsm[];
    float4* sy   = (float4*)dsm;          // 1024 float4
    float*  stre = dsm + 4096;            // l-major: [lrow][kloc], pad 65
    float*  stim = stre + TILE * TPAD;

    const int b   = blockIdx.x;
    const int tid = threadIdx.x;
    const int tx4 = tid & 15;
    const int ty  = tid >> 4;             // 0..15

    // Triangle index -> (ti, tj), tj >= ti
    int q = blockIdx.y, ti = 0, span = NT;
    while (q >= span) { q -= span; span--; ti++; }
    const int tj = ti + q;
    const int K0 = ti * TILE;
    const int L0 = tj * TILE;

    // Load y arrays (1024 float4 / 256 threads = 4 each)
    const float4* gy = g_y2 + b * (2 * N_DIM);
    #pragma unroll
    for (int i = 0; i < 4; i++) sy[tid + 256 * i] = gy[tid + 256 * i];
    __syncthreads();

    const int lbase = L0 + 4 * tx4;

    // conj-side operands for 4 l, premultiplied by mean scale 1/4
    float4 c01[4], c23[4];
    #pragma unroll
    for (int j = 0; j < 4; j++) {
        float4 v = sy[lbase + j];
        c01[j] = make_float4(v.x * 0.25f, v.y * 0.25f, v.z * 0.25f, v.w * 0.25f);
        v = sy[N_DIM + lbase + j];
        c23[j] = make_float4(v.x * 0.25f, v.y * 0.25f, v.z * 0.25f, v.w * 0.25f);
    }

    float* out_b = out + (size_t)b * (2u * NN);

    #pragma unroll
    for (int s = 0; s < 4; s++) {
        const int kloc = s * 16 + ty;
        const int k = K0 + kloc;
        const float4 A01 = sy[k];
        const float4 A23 = sy[N_DIM + k];
        const int m0 = (lbase - k) & (N_DIM - 1);

        float4 vre, vim;
        float* pre_ = &vre.x;   // component access via unrolled j
        float* pim_ = &vim.x;
        #pragma unroll
        for (int j = 0; j < 4; j++) {
            const int m = (m0 + j) & (N_DIM - 1);
            const float4 D01 = sy[m];
            const float4 D23 = sy[N_DIM + m];

            float are, aim;
            // t0
            float pr = A01.x * c01[j].x + A01.y * c01[j].y;
            float pi = A01.y * c01[j].x - A01.x * c01[j].y;
            are = pr * D01.x - pi * D01.y;
            aim = pr * D01.y + pi * D01.x;
            // t1
            pr = A01.z * c01[j].z + A01.w * c01[j].w;
            pi = A01.w * c01[j].z - A01.z * c01[j].w;
            are += pr * D01.z - pi * D01.w;
            aim += pr * D01.w + pi * D01.z;
            // t2
            pr = A23.x * c23[j].x + A23.y * c23[j].y;
            pi = A23.y * c23[j].x - A23.x * c23[j].y;
            are += pr * D23.x - pi * D23.y;
            aim += pr * D23.y + pi * D23.x;
            // t3
            pr = A23.z * c23[j].z + A23.w * c23[j].w;
            pi = A23.w * c23[j].z - A23.z * c23[j].w;
            are += pr * D23.z - pi * D23.w;
            aim += pr * D23.w + pi * D23.z;

            pre_[j] = are;
            pim_[j] = aim;

            // transpose buffers for the mirror tile (l-major)
            stre[(4 * tx4 + j) * TPAD + kloc] = are;
            stim[(4 * tx4 + j) * TPAD + kloc] = aim;
        }

        const unsigned o = (unsigned)(k * N_DIM + lbase);
        *(float4*)(out_b + o)      = vre;
        *(float4*)(out_b + o + NN) = vim;
    }

    if (ti == tj) return;                 // diagonal tile: no mirror

    __syncthreads();

    // Mirror tile: out[L0+r][K0+c] = conj(value at (k=K0+c, l=L0+r))
    #pragma unroll
    for (int s = 0; s < 4; s++) {
        const int r = s * 16 + ty;
        float4 vre, vim;
        vre.x = stre[r * TPAD + 4 * tx4 + 0];
        vre.y = stre[r * TPAD + 4 * tx4 + 1];
        vre.z = stre[r * TPAD + 4 * tx4 + 2];
        vre.w = stre[r * TPAD + 4 * tx4 + 3];
        vim.x = -stim[r * TPAD + 4 * tx4 + 0];
        vim.y = -stim[r * TPAD + 4 * tx4 + 1];
        vim.z = -stim[r * TPAD + 4 * tx4 + 2];
        vim.w = -stim[r * TPAD + 4 * tx4 + 3];
        const unsigned o = (unsigned)((L0 + r) * N_DIM + K0 + 4 * tx4);
        *(float4*)(out_b + o)      = vre;
        *(float4*)(out_b + o + NN) = vim;
    }
}

extern "C" void kernel_launch(void* const* d_in, const int* in_sizes, int n_in,
                              void* d_out, int out_size) {
    const float* target = (const float*)d_in[0];
    float* out = (float*)d_out;

    const int copy_tail = ((size_t)out_size >= SRC_ELEMS + TGT_ELEMS) ? 1 : 0;

    const int smem_bytes = (4096 + 2 * TILE * TPAD) * (int)sizeof(float);  // 49,664
    static bool attr_set = false;
    if (!attr_set) {
        cudaFuncSetAttribute(bispec_kernel,
                             cudaFuncAttributeMaxDynamicSharedMemorySize,
                             smem_bytes);
        attr_set = true;
    }

    fft512_kernel<<<NROWS, 256>>>(target, out, copy_tail);
    bispec_kernel<<<dim3(B_DIM, NTRI), 256, smem_bytes>>>(out);
}

// round 9
// speedup vs baseline: 1.3896x; 1.3896x over previous
#include <cuda_runtime.h>
#include <cuda_bf16.h>
#include <cstdint>

// BispectrumCalculator: target [B=32, T=4, N=512] f32
//   y = fft(target);  Bx[k,l] = y[k]*conj(y[l])*y[(l-k)%N]
//   source[b,{re,im},k,l] = mean_t Bx;  out = concat(source, target)
//
// Real input => Bx[l,k] = conj(Bx[k,l]) (Hermitian): compute upper-triangle
// 64x64 tiles only; emit mirror tile via padded smem transpose.
// This revision: 2 consecutive l per thread (STG.64), explicit scalar regs.

#define B_DIM 32
#define T_DIM 4
#define N_DIM 512
#define NROWS (B_DIM * T_DIM)                           // 128
#define SRC_ELEMS ((size_t)B_DIM * 2 * N_DIM * N_DIM)   // 16,777,216
#define TGT_ELEMS (B_DIM * T_DIM * N_DIM)               // 65,536
#define TILE 64
#define NT (N_DIM / TILE)                               // 8
#define NTRI (NT * (NT + 1) / 2)                        // 36
#define NN (N_DIM * N_DIM)                              // 262,144
#define TPAD 65                                         // transpose row pad

// FFT results, t-paired: g_y2[b][p][n] = float4(y_{2p}[n].re, y_{2p}[n].im,
//                                               y_{2p+1}[n].re, y_{2p+1}[n].im)
__device__ float4 g_y2[B_DIM * 2 * N_DIM];

// ---------------------------------------------------------------------------
// Kernel 1: 512-point radix-2 DIT FFT, one row per block, 256 threads.
//   Stages len<=64 are warp-local (warp w only touches s[64w .. 64w+63]),
//   so they need only __syncwarp(). Also copies the target tail.
// ---------------------------------------------------------------------------
__global__ void fft512_kernel(const float* __restrict__ x,
                              float* __restrict__ out, int copy_tail) {
    __shared__ float2 s[N_DIM];
    const int row = blockIdx.x;          // 0..127
    const int tid = threadIdx.x;         // 0..255
    const float* xr = x + row * N_DIM;

    if (copy_tail && tid < 128) {        // 128 float4 = 512 floats per row
        ((float4*)(out + SRC_ELEMS + (size_t)row * N_DIM))[tid] =
            ((const float4*)xr)[tid];
    }

    #pragma unroll
    for (int i = tid; i < N_DIM; i += 256) {
        int r = __brev((unsigned)i) >> 23;   // 9-bit bit reversal
        s[r] = make_float2(xr[i], 0.0f);
    }
    __syncthreads();

    #pragma unroll
    for (int len = 2; len <= N_DIM; len <<= 1) {
        int half = len >> 1;
        int j    = tid & (half - 1);
        int grp  = tid / half;
        int base = grp * len;
        float ang = -6.283185307179586f * (float)j / (float)len;
        float wr, wi;
        __sincosf(ang, &wi, &wr);
        float2 a = s[base + j];
        float2 b = s[base + j + half];
        float tr = wr * b.x - wi * b.y;
        float ti = wr * b.y + wi * b.x;
        s[base + j]        = make_float2(a.x + tr, a.y + ti);
        s[base + j + half] = make_float2(a.x - tr, a.y - ti);
        if (len <= 32)        __syncwarp();      // stage stays in warp's 64-range
        else if (len < N_DIM) __syncthreads();   // len=64..256: next stage crosses
        // len == 512: final store below reads this thread's own writes
    }

    // Paired store: row = b*4 + t -> half (t&1) of float4 at [b*2 + t/2][i]
    const int b = row >> 2, t = row & 3;
    float2* dst = (float2*)g_y2 + ((size_t)((b * 2 + (t >> 1)) * N_DIM)) * 2 + (t & 1);
    #pragma unroll
    for (int i = tid; i < N_DIM; i += 256)
        dst[i * 2] = s[i];
}

// ---------------------------------------------------------------------------
// Kernel 2: bispectrum on upper-triangle tiles, 2 consecutive l per thread.
//   grid = (32, 36); block = 512 threads.
//   tx2 = tid&31 -> l = L0 + 2*tx2 + {0,1};  ty = tid>>5 -> kloc = 16s + ty.
//   smem: sy[2][512] float4 (16KB) + stre/stim transpose [64][65] (33.3KB).
// ---------------------------------------------------------------------------
__global__ __launch_bounds__(512, 2)
void bispec_kernel(float* __restrict__ out) {
    extern __shared__ float dsm[];
    float4* sy   = (float4*)dsm;          // 1024 float4
    float*  stre = dsm + 4096;            // l-major: [lloc][kloc], pad 65
    float*  stim = stre + TILE * TPAD;

    const int b   = blockIdx.x;
    const int tid = threadIdx.x;
    const int tx2 = tid & 31;
    const int ty  = tid >> 5;             // 0..15

    // Triangle index -> (ti, tj), tj >= ti
    int q = blockIdx.y, ti = 0, span = NT;
    while (q >= span) { q -= span; span--; ti++; }
    const int tj = ti + q;
    const int K0 = ti * TILE;
    const int L0 = tj * TILE;

    // Load y arrays (1024 float4 / 512 threads = 2 each)
    const float4* gy = g_y2 + b * (2 * N_DIM);
    sy[tid]       = gy[tid];
    sy[tid + 512] = gy[tid + 512];
    __syncthreads();

    const int lloc0 = 2 * tx2;
    const int l0 = L0 + lloc0;

    // conj-side operands for l0, l0+1; premultiplied by mean scale 1/4
    float4 v;
    v = sy[l0];
    const float c01ax = v.x * 0.25f, c01ay = v.y * 0.25f,
                c01az = v.z * 0.25f, c01aw = v.w * 0.25f;
    v = sy[l0 + 1];
    const float c01bx = v.x * 0.25f, c01by = v.y * 0.25f,
                c01bz = v.z * 0.25f, c01bw = v.w * 0.25f;
    v = sy[N_DIM + l0];
    const float c23ax = v.x * 0.25f, c23ay = v.y * 0.25f,
                c23az = v.z * 0.25f, c23aw = v.w * 0.25f;
    v = sy[N_DIM + l0 + 1];
    const float c23bx = v.x * 0.25f, c23by = v.y * 0.25f,
                c23bz = v.z * 0.25f, c23bw = v.w * 0.25f;

    float* out_b = out + (size_t)b * (2u * NN);

    #pragma unroll
    for (int s = 0; s < 4; s++) {
        const int kloc = s * 16 + ty;
        const int k = K0 + kloc;
        const float4 A01 = sy[k];
        const float4 A23 = sy[N_DIM + k];
        const int m0 = (l0 - k) & (N_DIM - 1);
        const int m1 = (m0 + 1) & (N_DIM - 1);

        float are0, aim0, are1, aim1;
        float pr, pi;
        {   // l0
            const float4 D01 = sy[m0];
            const float4 D23 = sy[N_DIM + m0];
            pr = A01.x * c01ax + A01.y * c01ay;
            pi = A01.y * c01ax - A01.x * c01ay;
            are0 = pr * D01.x - pi * D01.y;
            aim0 = pr * D01.y + pi * D01.x;
            pr = A01.z * c01az + A01.w * c01aw;
            pi = A01.w * c01az - A01.z * c01aw;
            are0 += pr * D01.z - pi * D01.w;
            aim0 += pr * D01.w + pi * D01.z;
            pr = A23.x * c23ax + A23.y * c23ay;
            pi = A23.y * c23ax - A23.x * c23ay;
            are0 += pr * D23.x - pi * D23.y;
            aim0 += pr * D23.y + pi * D23.x;
            pr = A23.z * c23az + A23.w * c23aw;
            pi = A23.w * c23az - A23.z * c23aw;
            are0 += pr * D23.z - pi * D23.w;
            aim0 += pr * D23.w + pi * D23.z;
        }
        {   // l0 + 1
            const float4 D01 = sy[m1];
            const float4 D23 = sy[N_DIM + m1];
            pr = A01.x * c01bx + A01.y * c01by;
            pi = A01.y * c01bx - A01.x * c01by;
            are1 = pr * D01.x - pi * D01.y;
            aim1 = pr * D01.y + pi * D01.x;
            pr = A01.z * c01bz + A01.w * c01bw;
            pi = A01.w * c01bz - A01.z * c01bw;
            are1 += pr * D01.z - pi * D01.w;
            aim1 += pr * D01.w + pi * D01.z;
            pr = A23.x * c23bx + A23.y * c23by;
            pi = A23.y * c23bx - A23.x * c23by;
            are1 += pr * D23.x - pi * D23.y;
            aim1 += pr * D23.y + pi * D23.x;
            pr = A23.z * c23bz + A23.w * c23bw;
            pi = A23.w * c23bz - A23.z * c23bw;
            are1 += pr * D23.z - pi * D23.w;
            aim1 += pr * D23.w + pi * D23.z;
        }

        const unsigned o = (unsigned)(k * N_DIM + l0);
        *(float2*)(out_b + o)      = make_float2(are0, are1);
        *(float2*)(out_b + o + NN) = make_float2(aim0, aim1);

        // transpose buffers for the mirror tile (l-major)
        stre[lloc0 * TPAD + kloc]       = are0;
        stre[(lloc0 + 1) * TPAD + kloc] = are1;
        stim[lloc0 * TPAD + kloc]       = aim0;
        stim[(lloc0 + 1) * TPAD + kloc] = aim1;
    }

    if (ti == tj) return;                 // diagonal tile: no mirror

    __syncthreads();

    // Mirror tile: out[L0+r][K0+c] = conj(value at (k=K0+c, l=L0+r))
    #pragma unroll
    for (int s = 0; s < 4; s++) {
        const int r = s * 16 + ty;
        const float re0 = stre[r * TPAD + lloc0];
        const float re1 = stre[r * TPAD + lloc0 + 1];
        const float im0 = stim[r * TPAD + lloc0];
        const float im1 = stim[r * TPAD + lloc0 + 1];
        const unsigned o = (unsigned)((L0 + r) * N_DIM + K0 + lloc0);
        *(float2*)(out_b + o)      = make_float2(re0, re1);
        *(float2*)(out_b + o + NN) = make_float2(-im0, -im1);
    }
}

extern "C" void kernel_launch(void* const* d_in, const int* in_sizes, int n_in,
                              void* d_out, int out_size) {
    const float* target = (const float*)d_in[0];
    float* out = (float*)d_out;

    const int copy_tail = ((size_t)out_size >= SRC_ELEMS + TGT_ELEMS) ? 1 : 0;

    const int smem_bytes = (4096 + 2 * TILE * TPAD) * (int)sizeof(float);  // 49,664
    static bool attr_set = false;
    if (!attr_set) {
        cudaFuncSetAttribute(bispec_kernel,
                             cudaFuncAttributeMaxDynamicSharedMemorySize,
                             smem_bytes);
        attr_set = true;
    }

    fft512_kernel<<<NROWS, 256>>>(target, out, copy_tail);
    bispec_kernel<<<dim3(B_DIM, NTRI), 512, smem_bytes>>>(out);
}

// round 10
// speedup vs baseline: 1.6190x; 1.1651x over previous
#include <cuda_runtime.h>
#include <cuda_bf16.h>
#include <cstdint>

// BispectrumCalculator: target [B=32, T=4, N=512] f32
//   y = fft(target);  Bx[k,l] = y[k]*conj(y[l])*y[(l-k)%N]
//   source[b,{re,im},k,l] = mean_t Bx;  out = concat(source, target)
//
// Real input => Bx[l,k] = conj(Bx[k,l]) (Hermitian): compute upper-triangle
// 64x64 tiles only; emit mirror tile via padded smem transpose.
// Best-known config: 1 l per thread, 512 thr, 3 blocks/SM (40-reg budget).

#define B_DIM 32
#define T_DIM 4
#define N_DIM 512
#define NROWS (B_DIM * T_DIM)                           // 128
#define SRC_ELEMS ((size_t)B_DIM * 2 * N_DIM * N_DIM)   // 16,777,216
#define TGT_ELEMS (B_DIM * T_DIM * N_DIM)               // 65,536
#define TILE 64
#define NT (N_DIM / TILE)                               // 8
#define NTRI (NT * (NT + 1) / 2)                        // 36
#define NN (N_DIM * N_DIM)                              // 262,144

// FFT results, t-paired: g_y2[b][p][n] = float4(y_{2p}[n].re, y_{2p}[n].im,
//                                               y_{2p+1}[n].re, y_{2p+1}[n].im)
__device__ float4 g_y2[B_DIM * 2 * N_DIM];

// ---------------------------------------------------------------------------
// Kernel 1: 512-point radix-2 DIT FFT, one row per block, 256 threads.
//   Stages len<=32 are warp-local (warp w only touches s[64w .. 64w+63]),
//   so they need only __syncwarp(). Also copies the target tail.
// ---------------------------------------------------------------------------
__global__ void fft512_kernel(const float* __restrict__ x,
                              float* __restrict__ out, int copy_tail) {
    __shared__ float2 s[N_DIM];
    const int row = blockIdx.x;          // 0..127
    const int tid = threadIdx.x;         // 0..255
    const float* xr = x + row * N_DIM;

    if (copy_tail && tid < 128) {        // 128 float4 = 512 floats per row
        ((float4*)(out + SRC_ELEMS + (size_t)row * N_DIM))[tid] =
            ((const float4*)xr)[tid];
    }

    #pragma unroll
    for (int i = tid; i < N_DIM; i += 256) {
        int r = __brev((unsigned)i) >> 23;   // 9-bit bit reversal
        s[r] = make_float2(xr[i], 0.0f);
    }
    __syncthreads();

    #pragma unroll
    for (int len = 2; len <= N_DIM; len <<= 1) {
        int half = len >> 1;
        int j    = tid & (half - 1);
        int grp  = tid / half;
        int base = grp * len;
        float ang = -6.283185307179586f * (float)j / (float)len;
        float wr, wi;
        __sincosf(ang, &wi, &wr);
        float2 a = s[base + j];
        float2 b = s[base + j + half];
        float tr = wr * b.x - wi * b.y;
        float ti = wr * b.y + wi * b.x;
        s[base + j]        = make_float2(a.x + tr, a.y + ti);
        s[base + j + half] = make_float2(a.x - tr, a.y - ti);
        if (len <= 32)        __syncwarp();      // stage stays in warp's 64-range
        else if (len < N_DIM) __syncthreads();   // len=64..256: next stage crosses
        // len == 512: final store below reads this thread's own writes
    }

    // Paired store: row = b*4 + t -> half (t&1) of float4 at [b*2 + t/2][i]
    const int b = row >> 2, t = row & 3;
    float2* dst = (float2*)g_y2 + ((size_t)((b * 2 + (t >> 1)) * N_DIM)) * 2 + (t & 1);
    #pragma unroll
    for (int i = tid; i < N_DIM; i += 256)
        dst[i * 2] = s[i];
}

// ---------------------------------------------------------------------------
// Kernel 2: bispectrum on upper-triangle tiles (R7 structure).
//   grid = (32, 36); block = 512 threads (thread = l within tile).
//   Dynamic smem: sy[2][512] float4 (16KB) + stre/stim[64][65] (33.3KB).
//   Diagonal tiles skip the transpose-buffer stores (mirror path unused).
// ---------------------------------------------------------------------------
__global__ __launch_bounds__(512, 3)
void bispec_kernel(float* __restrict__ out) {
    extern __shared__ float dsm[];
    float4* sy   = (float4*)dsm;          // 1024 float4
    float*  stre = dsm + 4096;            // 64*65 floats
    float*  stim = stre + 64 * 65;

    const int b   = blockIdx.x;
    const int tid = threadIdx.x;
    const int tx  = tid & 63;             // l within tile
    const int tyg = tid >> 6;             // 0..7, k sub-group

    // Triangle index -> (ti, tj), tj >= ti
    int q = blockIdx.y, ti = 0, span = NT;
    while (q >= span) { q -= span; span--; ti++; }
    const int tj = ti + q;
    const int K0 = ti * TILE;
    const int L0 = tj * TILE;
    const bool offdiag = (ti != tj);

    // Load y tile-pair arrays (1024 float4 / 512 threads = 2 each)
    const float4* gy = g_y2 + b * (2 * N_DIM);
    sy[tid]       = gy[tid];
    sy[tid + 512] = gy[tid + 512];
    __syncthreads();

    const int l = L0 + tx;
    const float4 c01 = sy[l];             // conj side, t0/t1
    const float4 c23 = sy[N_DIM + l];     // conj side, t2/t3

    // 32-bit addressing: per-batch base, element offsets < 2^25
    float* out_b = out + (size_t)b * (2u * NN);

    #pragma unroll
    for (int kk = 0; kk < 8; kk++) {
        const int kloc = tyg * 8 + kk;
        const int k = K0 + kloc;
        const int m = (l - k) & (N_DIM - 1);

        float are, aim;
        {
            float4 A = sy[k];
            float4 D = sy[m];
            float pre = A.x * c01.x + A.y * c01.y;
            float pim = A.y * c01.x - A.x * c01.y;
            are = pre * D.x - pim * D.y;
            aim = pre * D.y + pim * D.x;
            pre = A.z * c01.z + A.w * c01.w;
            pim = A.w * c01.z - A.z * c01.w;
            are += pre * D.z - pim * D.w;
            aim += pre * D.w + pim * D.z;
        }
        {
            float4 A = sy[N_DIM + k];
            float4 D = sy[N_DIM + m];
            float pre = A.x * c23.x + A.y * c23.y;
            float pim = A.y * c23.x - A.x * c23.y;
            are += pre * D.x - pim * D.y;
            aim += pre * D.y + pim * D.x;
            pre = A.z * c23.z + A.w * c23.w;
            pim = A.w * c23.z - A.z * c23.w;
            are += pre * D.z - pim * D.w;
            aim += pre * D.w + pim * D.z;
        }
        are *= 0.25f;
        aim *= 0.25f;

        const unsigned o = (unsigned)(k * N_DIM + l);
        out_b[o]      = are;
        out_b[o + NN] = aim;
        if (offdiag) {                    // transpose buffers only when mirrored
            stre[kloc * 65 + tx] = are;
            stim[kloc * 65 + tx] = aim;
        }
    }

    if (!offdiag) return;                 // diagonal tile: no mirror

    __syncthreads();

    // Mirror tile: out[L0+r][K0+tx] = conj(Bx[K0+tx][L0+r])
    #pragma unroll
    for (int kk = 0; kk < 8; kk++) {
        const int r = tyg * 8 + kk;
        const float re = stre[tx * 65 + r];
        const float im = stim[tx * 65 + r];
        const unsigned o = (unsigned)((L0 + r) * N_DIM + (K0 + tx));
        out_b[o]      = re;
        out_b[o + NN] = -im;
    }
}

extern "C" void kernel_launch(void* const* d_in, const int* in_sizes, int n_in,
                              void* d_out, int out_size) {
    const float* target = (const float*)d_in[0];
    float* out = (float*)d_out;

    const int copy_tail = ((size_t)out_size >= SRC_ELEMS + TGT_ELEMS) ? 1 : 0;

    const int smem_bytes = (4096 + 2 * 64 * 65) * (int)sizeof(float);  // 49,664
    static bool attr_set = false;
    if (!attr_set) {
        cudaFuncSetAttribute(bispec_kernel,
                             cudaFuncAttributeMaxDynamicSharedMemorySize,
                             smem_bytes);
        attr_set = true;
    }

    fft512_kernel<<<NROWS, 256>>>(target, out, copy_tail);
    bispec_kernel<<<dim3(B_DIM, NTRI), 512, smem_bytes>>>(out);
}

// round 11
// speedup vs baseline: 1.7969x; 1.1099x over previous
#include <cuda_runtime.h>
#include <cuda_bf16.h>
#include <cstdint>

// BispectrumCalculator: target [B=32, T=4, N=512] f32
//   y = fft(target);  Bx[k,l] = y[k]*conj(y[l])*y[(l-k)%N]
//   source[b,{re,im},k,l] = mean_t Bx;  out = concat(source, target)
//
// Real input symmetries:
//   Bx[(N-k)%N, (N-l)%N] = conj(Bx[k,l])   (negation symmetry — used here)
// Compute rows k=0..255 fully; mirror rows 257..511 via register-direct
// reversed stores (no smem transpose). Row 256 is self-symmetric -> own block.

#define B_DIM 32
#define T_DIM 4
#define N_DIM 512
#define NROWS (B_DIM * T_DIM)                           // 128
#define SRC_ELEMS ((size_t)B_DIM * 2 * N_DIM * N_DIM)   // 16,777,216
#define TGT_ELEMS (B_DIM * T_DIM * N_DIM)               // 65,536
#define TILE 64
#define NTILES 33                                       // 4*8 main + 1 (row 256)
#define NN (N_DIM * N_DIM)                              // 262,144

// FFT results, t-paired: g_y2[b][p][n] = float4(y_{2p}[n].re, y_{2p}[n].im,
//                                               y_{2p+1}[n].re, y_{2p+1}[n].im)
__device__ float4 g_y2[B_DIM * 2 * N_DIM];

// ---------------------------------------------------------------------------
// Kernel 1: 512-point radix-2 DIT FFT, one row per block, 256 threads.
//   Stages len<=32 are warp-local; final stage needs no sync before store.
//   Also copies the target tail into the output.
// ---------------------------------------------------------------------------
__global__ void fft512_kernel(const float* __restrict__ x,
                              float* __restrict__ out, int copy_tail) {
    __shared__ float2 s[N_DIM];
    const int row = blockIdx.x;          // 0..127
    const int tid = threadIdx.x;         // 0..255
    const float* xr = x + row * N_DIM;

    if (copy_tail && tid < 128) {        // 128 float4 = 512 floats per row
        ((float4*)(out + SRC_ELEMS + (size_t)row * N_DIM))[tid] =
            ((const float4*)xr)[tid];
    }

    #pragma unroll
    for (int i = tid; i < N_DIM; i += 256) {
        int r = __brev((unsigned)i) >> 23;   // 9-bit bit reversal
        s[r] = make_float2(xr[i], 0.0f);
    }
    __syncthreads();

    #pragma unroll
    for (int len = 2; len <= N_DIM; len <<= 1) {
        int half = len >> 1;
        int j    = tid & (half - 1);
        int grp  = tid / half;
        int base = grp * len;
        float ang = -6.283185307179586f * (float)j / (float)len;
        float wr, wi;
        __sincosf(ang, &wi, &wr);
        float2 a = s[base + j];
        float2 b = s[base + j + half];
        float tr = wr * b.x - wi * b.y;
        float ti = wr * b.y + wi * b.x;
        s[base + j]        = make_float2(a.x + tr, a.y + ti);
        s[base + j + half] = make_float2(a.x - tr, a.y - ti);
        if (len <= 32)        __syncwarp();      // stage stays in warp's 64-range
        else if (len < N_DIM) __syncthreads();   // len=64..256: next stage crosses
        // len == 512: final store below reads this thread's own writes
    }

    // Paired store: row = b*4 + t -> half (t&1) of float4 at [b*2 + t/2][i]
    const int b = row >> 2, t = row & 3;
    float2* dst = (float2*)g_y2 + ((size_t)((b * 2 + (t >> 1)) * N_DIM)) * 2 + (t & 1);
    #pragma unroll
    for (int i = tid; i < N_DIM; i += 256)
        dst[i * 2] = s[i];
}

// ---------------------------------------------------------------------------
// Kernel 2: bispectrum, negation-symmetry halving.
//   grid = (32, 33); block = 512 threads.
//   tile_id 0..31: ti = id>>3 (k tile 0..3), tj = id&7 (l tile).
//     thread tx = l-within-tile, tyg*8+kk = k-within-tile.
//     direct store at [k][l]; mirror store at [(-k)&511][(-l)&511] = conj.
//   tile_id 32: row k=256 (self-symmetric), thread = l, direct only.
//   smem: sy[2][512] float4 = 16KB static.
// ---------------------------------------------------------------------------
__global__ __launch_bounds__(512, 3)
void bispec_kernel(float* __restrict__ out) {
    __shared__ float4 sy[2 * N_DIM];

    const int b   = blockIdx.x;
    const int id  = blockIdx.y;
    const int tid = threadIdx.x;

    // Load y arrays (1024 float4 / 512 threads = 2 each)
    const float4* gy = g_y2 + b * (2 * N_DIM);
    sy[tid]       = gy[tid];
    sy[tid + 512] = gy[tid + 512];
    __syncthreads();

    float* out_b = out + (size_t)b * (2u * NN);

    if (id == 32) {
        // Row k = 256: Bx[256, l] for all l. One output per thread.
        const int l = tid;
        const int m = (l - 256) & (N_DIM - 1);
        const float4 A01 = sy[256];
        const float4 A23 = sy[N_DIM + 256];
        const float4 c01 = sy[l];
        const float4 c23 = sy[N_DIM + l];
        const float4 D01 = sy[m];
        const float4 D23 = sy[N_DIM + m];

        float pre = A01.x * c01.x + A01.y * c01.y;
        float pim = A01.y * c01.x - A01.x * c01.y;
        float are = pre * D01.x - pim * D01.y;
        float aim = pre * D01.y + pim * D01.x;
        pre = A01.z * c01.z + A01.w * c01.w;
        pim = A01.w * c01.z - A01.z * c01.w;
        are += pre * D01.z - pim * D01.w;
        aim += pre * D01.w + pim * D01.z;
        pre = A23.x * c23.x + A23.y * c23.y;
        pim = A23.y * c23.x - A23.x * c23.y;
        are += pre * D23.x - pim * D23.y;
        aim += pre * D23.y + pim * D23.x;
        pre = A23.z * c23.z + A23.w * c23.w;
        pim = A23.w * c23.z - A23.z * c23.w;
        are += pre * D23.z - pim * D23.w;
        aim += pre * D23.w + pim * D23.z;

        const unsigned o = (unsigned)(256 * N_DIM + l);
        out_b[o]      = are * 0.25f;
        out_b[o + NN] = aim * 0.25f;
        return;
    }

    const int ti = id >> 3;               // 0..3  -> K0 = 0..192
    const int tj = id & 7;                // 0..7  -> L0
    const int K0 = ti * TILE;
    const int L0 = tj * TILE;
    const int tx  = tid & 63;             // l within tile
    const int tyg = tid >> 6;             // 0..7, k sub-group

    const int l = L0 + tx;
    const float4 c01 = sy[l];             // conj side, t0/t1
    const float4 c23 = sy[N_DIM + l];     // conj side, t2/t3
    const unsigned lneg = (unsigned)((N_DIM - l) & (N_DIM - 1));  // (-l) mod N

    #pragma unroll
    for (int kk = 0; kk < 8; kk++) {
        const int k = K0 + tyg * 8 + kk;  // 0..255
        const int m = (l - k) & (N_DIM - 1);

        float are, aim;
        {
            float4 A = sy[k];
            float4 D = sy[m];
            float pre = A.x * c01.x + A.y * c01.y;
            float pim = A.y * c01.x - A.x * c01.y;
            are = pre * D.x - pim * D.y;
            aim = pre * D.y + pim * D.x;
            pre = A.z * c01.z + A.w * c01.w;
            pim = A.w * c01.z - A.z * c01.w;
            are += pre * D.z - pim * D.w;
            aim += pre * D.w + pim * D.z;
        }
        {
            float4 A = sy[N_DIM + k];
            float4 D = sy[N_DIM + m];
            float pre = A.x * c23.x + A.y * c23.y;
            float pim = A.y * c23.x - A.x * c23.y;
            are += pre * D.x - pim * D.y;
            aim += pre * D.y + pim * D.x;
            pre = A.z * c23.z + A.w * c23.w;
            pim = A.w * c23.z - A.z * c23.w;
            are += pre * D.z - pim * D.w;
            aim += pre * D.w + pim * D.z;
        }
        are *= 0.25f;
        aim *= 0.25f;

        // Direct: [k][l]
        const unsigned o = (unsigned)(k * N_DIM + l);
        out_b[o]      = are;
        out_b[o + NN] = aim;

        // Mirror: [(-k)%N][(-l)%N] = conj  (k=0 mirrors onto row 0: skip,
        // direct coverage of row 0 already writes those elements)
        if (k) {
            const unsigned om = (unsigned)((N_DIM - k) * N_DIM) + lneg;
            out_b[om]      = are;
            out_b[om + NN] = -aim;
        }
    }
}

extern "C" void kernel_launch(void* const* d_in, const int* in_sizes, int n_in,
                              void* d_out, int out_size) {
    const float* target = (const float*)d_in[0];
    float* out = (float*)d_out;

    const int copy_tail = ((size_t)out_size >= SRC_ELEMS + TGT_ELEMS) ? 1 : 0;

    fft512_kernel<<<NROWS, 256>>>(target, out, copy_tail);
    bispec_kernel<<<dim3(B_DIM, NTILES), 512>>>(out);
}